// round 2
// baseline (speedup 1.0000x reference)
#include <cuda_runtime.h>
#include <math_constants.h>

#define BATCH 262144
#define NLAYER 8
#define H 128
#define NSEG 129
#define BN_EPS 1e-5f
#define FLOW_EPS 1e-4f

// ---------------- device scratch (no allocs allowed) ----------------
__device__ double g_sum[2];                    // sum(u), sum(u^2) for current layer input
__device__ double g_segN[NSEG], g_segS1[NSEG], g_segS2[NSEG];
__device__ float  g_theta[H];                  // sorted kinks
__device__ __align__(16) float g_tab[NSEG * H * 2];  // [m][j]{A,B} -> folded {alpha,gamma}
__device__ unsigned char g_mseg[BATCH];
__device__ float g_x[2 * BATCH];
__device__ float g_sldj[BATCH];

// ---------------- init: copy x, zero sldj, stats of x1 (layer0 input) ----------------
__global__ void k_init(const float* __restrict__ x)
{
    int tid = blockIdx.x * blockDim.x + threadIdx.x;
    int stride = gridDim.x * blockDim.x;
    double s = 0.0, q = 0.0;
    for (int i = tid; i < BATCH; i += stride) {
        float2 p = ((const float2*)x)[i];
        ((float2*)g_x)[i] = p;
        g_sldj[i] = 0.f;
        s += (double)p.y;
        q += (double)p.y * (double)p.y;
    }
    // block reduce -> global atomics
    for (int off = 16; off; off >>= 1) {
        s += __shfl_down_sync(0xffffffffu, s, off);
        q += __shfl_down_sync(0xffffffffu, q, off);
    }
    __shared__ double ss[32], sq[32];
    int lane = threadIdx.x & 31, w = threadIdx.x >> 5;
    if (!lane) { ss[w] = s; sq[w] = q; }
    __syncthreads();
    if (!w) {
        int nw = blockDim.x >> 5;
        s = (lane < nw) ? ss[lane] : 0.0;
        q = (lane < nw) ? sq[lane] : 0.0;
        for (int off = 16; off; off >>= 1) {
            s += __shfl_down_sync(0xffffffffu, s, off);
            q += __shfl_down_sync(0xffffffffu, q, off);
        }
        if (!lane) { atomicAdd(&g_sum[0], s); atomicAdd(&g_sum[1], q); }
    }
}

// ---------------- prep: fold BN1, sort kinks, build segment A/B table ----------------
// one block, 128 threads. dyn smem: sa,sc,sthr,sths (4*H f), sord (H int), sv2 (H*129 f)
__global__ void k_prep(int l,
    const float* __restrict__ v1, const float* __restrict__ g1, const float* __restrict__ b1,
    const float* __restrict__ bn1g, const float* __restrict__ bn1b,
    const float* __restrict__ v2, const float* __restrict__ g2, const float* __restrict__ b2)
{
    extern __shared__ float smp[];
    float* sa   = smp;
    float* sc   = sa + H;
    float* sthr = sc + H;
    float* sths = sthr + H;
    int*   sord = (int*)(sths + H);
    float* sv2  = (float*)(sord + H);   // [j][k] padded stride 129

    int k = threadIdx.x;   // 0..127
    double mu  = g_sum[0] * (1.0 / BATCH);
    double var = g_sum[1] * (1.0 / BATCH) - mu * mu;
    float meanu = (float)mu;
    float varu  = (float)(var < 0.0 ? 0.0 : var);

    float v  = v1[l * H + k];
    float w1 = g1[l * H + k] * (v / fabsf(v));
    float r  = rsqrtf(w1 * w1 * varu + BN_EPS);
    float a  = w1 * bn1g[l * H + k] * r;
    float c  = bn1b[l * H + k] - a * meanu;
    sa[k] = a; sc[k] = c;
    float th = (a != 0.f) ? (-c / a) : CUDART_INF_F;
    sthr[k] = th;
    __syncthreads();

    // rank-sort the 128 kinks (all-pairs, tie-break by index)
    int rank = 0;
    for (int j = 0; j < H; j++) {
        float tj = sthr[j];
        rank += (tj < th) || (tj == th && j < k);
    }
    sths[rank] = th;
    sord[rank] = k;
    g_theta[rank] = th;

    // load v2[l] into padded smem [j][k] (stride 129 -> conflict-free column access)
    for (int idx = k; idx < H * H; idx += H) {
        int row = idx >> 7, col = idx & 127;
        sv2[row * 129 + col] = v2[l * H * H + idx];
    }
    __syncthreads();

    int j = k;  // output feature this thread owns
    float nrm = 0.f;
    for (int t = 0; t < H; t++) { float x = sv2[j * 129 + t]; nrm = fmaf(x, x, nrm); }
    float wsc = g2[l * H + j] / sqrtf(nrm);

    // base segment (u -> -inf): active iff a<0 (or a==0 && c>0 constant)
    float A = 0.f, Bv = b2[l * H + j];
    for (int t = 0; t < H; t++) {
        float aa = sa[t], cc = sc[t];
        float w = wsc * sv2[j * 129 + t];
        if (aa < 0.f)                     { A += w * aa; Bv += w * cc; }
        else if (aa == 0.f && cc > 0.f)   { Bv += w * cc; }
    }
    g_tab[(0 * H + j) * 2]     = A;
    g_tab[(0 * H + j) * 2 + 1] = Bv;

    // walk kinks in ascending order
    for (int m = 1; m <= H; m++) {
        int kk = sord[m - 1];
        float aa = sa[kk], cc = sc[kk];
        float w = wsc * sv2[j * 129 + kk];
        float sgn = (aa > 0.f) ? 1.f : ((aa < 0.f) ? -1.f : 0.f);
        A  += sgn * w * aa;
        Bv += sgn * w * cc;
        g_tab[(m * H + j) * 2]     = A;
        g_tab[(m * H + j) * 2 + 1] = Bv;
    }

    // zero segment stats for the histogram pass
    for (int i = k; i < NSEG; i += H) { g_segN[i] = 0.0; g_segS1[i] = 0.0; g_segS2[i] = 0.0; }
}

// ---------------- hist: per-sample segment + sufficient statistics ----------------
__global__ void k_hist(int uIdx)
{
    __shared__ float sth[H];
    __shared__ double sN[NSEG], s1[NSEG], s2[NSEG];
    int t = threadIdx.x;
    for (int i = t; i < H; i += blockDim.x) sth[i] = g_theta[i];
    for (int i = t; i < NSEG; i += blockDim.x) { sN[i] = 0.0; s1[i] = 0.0; s2[i] = 0.0; }
    __syncthreads();

    int tid = blockIdx.x * blockDim.x + t;
    int stride = gridDim.x * blockDim.x;
    for (int i = tid; i < BATCH; i += stride) {
        float2 p = ((const float2*)g_x)[i];
        float u = uIdx ? p.y : p.x;
        int m = 0;
#pragma unroll
        for (int s = 64; s >= 1; s >>= 1) { int nm = m + s; if (sth[nm - 1] < u) m = nm; }
        // the 7-step count saturates at 127; count==128 iff max kink < u
        if (sth[H - 1] < u) m = H;
        g_mseg[i] = (unsigned char)m;
        atomicAdd(&sN[m], 1.0);
        atomicAdd(&s1[m], (double)u);
        atomicAdd(&s2[m], (double)u * (double)u);
    }
    __syncthreads();
    for (int i = t; i < NSEG; i += blockDim.x) {
        if (sN[i] != 0.0) {
            atomicAdd(&g_segN[i],  sN[i]);
            atomicAdd(&g_segS1[i], s1[i]);
            atomicAdd(&g_segS2[i], s2[i]);
        }
    }
}

// ---------------- fold: BN2 stats from segment sufficient stats, fold into table ----------------
__global__ void k_fold(int l, const float* __restrict__ bn2g, const float* __restrict__ bn2b)
{
    int j = threadIdx.x;   // 0..127
    double am0 = 0, am1 = 0, aq0 = 0, aq1 = 0;  // split accumulators (break DADD chain)
    for (int m = 0; m < NSEG; m++) {
        float A  = g_tab[(m * H + j) * 2];
        float Bv = g_tab[(m * H + j) * 2 + 1];
        double N  = g_segN[m];
        double S1 = g_segS1[m];
        double S2 = g_segS2[m];
        double t1 = (double)A * S1 + (double)Bv * N;
        double t2 = (double)A * A * S2 + 2.0 * (double)A * (double)Bv * S1 + (double)Bv * (double)Bv * N;
        if (m & 1) { am1 += t1; aq1 += t2; } else { am0 += t1; aq0 += t2; }
    }
    double mean = (am0 + am1) * (1.0 / BATCH);
    double var  = (aq0 + aq1) * (1.0 / BATCH) - mean * mean;
    if (var < 0.0) var = 0.0;
    float gh = bn2g[l * H + j] * rsqrtf((float)var + BN_EPS);
    float bh = bn2b[l * H + j] - gh * (float)mean;
    for (int m = 0; m < NSEG; m++) {
        float A  = g_tab[(m * H + j) * 2];
        float Bv = g_tab[(m * H + j) * 2 + 1];
        g_tab[(m * H + j) * 2]     = gh * A;
        g_tab[(m * H + j) * 2 + 1] = fmaf(gh, Bv, bh);
    }
    if (j < 2) g_sum[j] = 0.0;   // reset for next-layer input stats
}

// ---------------- apply: per-sample output (warp-per-sample cooperative gather) ----------------
__global__ void __launch_bounds__(512, 1) k_apply(
    int uIdx, int isLast, int l,
    const float* __restrict__ wf, const float* __restrict__ bf,
    float* __restrict__ out)
{
    extern __shared__ float2 stab[];            // NSEG*H table + H wf pairs
    float2* wfp = stab + NSEG * H;
    {
        float4* dst = (float4*)stab;
        const float4* src = (const float4*)g_tab;
        for (int i = threadIdx.x; i < (NSEG * H) / 2; i += blockDim.x) dst[i] = src[i];
    }
    for (int jj = threadIdx.x; jj < H; jj += blockDim.x)
        wfp[jj] = make_float2(wf[(l * 2 + 0) * H + jj], wf[(l * 2 + 1) * H + jj]);
    __syncthreads();

    int lane = threadIdx.x & 31, wid = threadIdx.x >> 5;
    // this lane covers j = {2*lane, 2*lane+1, 2*lane+64, 2*lane+65}
    float2 wA = wfp[2 * lane], wB = wfp[2 * lane + 1];
    float2 wC = wfp[2 * lane + 64], wD = wfp[2 * lane + 65];
    float bf0 = bf[l * 2], bf1 = bf[l * 2 + 1];
    int oIdx = 1 - uIdx;

    double accS = 0.0, accQ = 0.0;
    int gw = blockIdx.x * (blockDim.x >> 5) + wid;
    int nw = gridDim.x * (blockDim.x >> 5);

    for (int base = gw * 32; base < BATCH; base += nw * 32) {
        int i = base + lane;
        float2 p = ((const float2*)g_x)[i];
        float u  = uIdx ? p.y : p.x;
        float xo = uIdx ? p.x : p.y;
        int m = g_mseg[i];
        float sld = g_sldj[i];
        float st0r = 0.f, st1r = 0.f;
#pragma unroll 4
        for (int s = 0; s < 32; s++) {
            float us = __shfl_sync(0xffffffffu, u, s);
            int   ms = __shfl_sync(0xffffffffu, m, s);
            const float4* row = (const float4*)(stab + ms * H);
            float4 pAB = row[lane];         // j = 2*lane, 2*lane+1
            float4 pCD = row[lane + 32];    // j = 2*lane+64, 2*lane+65
            float hA = fmaxf(fmaf(pAB.x, us, pAB.y), 0.f);
            float hB = fmaxf(fmaf(pAB.z, us, pAB.w), 0.f);
            float hC = fmaxf(fmaf(pCD.x, us, pCD.y), 0.f);
            float hD = fmaxf(fmaf(pCD.z, us, pCD.w), 0.f);
            float p0 = fmaf(wA.x, hA, fmaf(wB.x, hB, fmaf(wC.x, hC, wD.x * hD)));
            float p1 = fmaf(wA.y, hA, fmaf(wB.y, hB, fmaf(wC.y, hC, wD.y * hD)));
#pragma unroll
            for (int off = 16; off; off >>= 1) {
                p0 += __shfl_xor_sync(0xffffffffu, p0, off);
                p1 += __shfl_xor_sync(0xffffffffu, p1, off);
            }
            if (lane == s) { st0r = p0; st1r = p1; }
        }
        float st0 = st0r + bf0;
        float st1 = st1r + bf1;
        float sv = tanhf(st0);
        float y  = fmaf(expf(sv), xo, st1);
        sld += sv;
        if (!isLast) {
            g_x[2 * i + oIdx] = y;
            g_sldj[i] = sld;
            accS += (double)y;
            accQ += (double)y * (double)y;
        } else {
            float zu = 1.f / (1.f + expf(-u));
            float zo = 1.f / (1.f + expf(-y));
            sld += logf(zu * (1.f - zu) + FLOW_EPS) + logf(zo * (1.f - zo) + FLOW_EPS);
            out[2 * i + uIdx] = zu;
            out[2 * i + oIdx] = zo;
            out[2 * BATCH + i] = sld;
        }
    }

    if (!isLast) {
        for (int off = 16; off; off >>= 1) {
            accS += __shfl_down_sync(0xffffffffu, accS, off);
            accQ += __shfl_down_sync(0xffffffffu, accQ, off);
        }
        __shared__ double rs[16], rq[16];
        if (!lane) { rs[wid] = accS; rq[wid] = accQ; }
        __syncthreads();
        if (!wid) {
            int nwb = blockDim.x >> 5;
            double s = (lane < nwb) ? rs[lane] : 0.0;
            double q = (lane < nwb) ? rq[lane] : 0.0;
            for (int off = 16; off; off >>= 1) {
                s += __shfl_down_sync(0xffffffffu, s, off);
                q += __shfl_down_sync(0xffffffffu, q, off);
            }
            if (!lane) { atomicAdd(&g_sum[0], s); atomicAdd(&g_sum[1], q); }
        }
    }
}

// ---------------- host launcher ----------------
extern "C" void kernel_launch(void* const* d_in, const int* in_sizes, int n_in,
                              void* d_out, int out_size)
{
    const float* x    = (const float*)d_in[0];
    const float* v1   = (const float*)d_in[1];
    const float* g1   = (const float*)d_in[2];
    const float* b1   = (const float*)d_in[3];
    const float* bn1g = (const float*)d_in[4];
    const float* bn1b = (const float*)d_in[5];
    const float* v2   = (const float*)d_in[6];
    const float* g2   = (const float*)d_in[7];
    const float* b2   = (const float*)d_in[8];
    const float* bn2g = (const float*)d_in[9];
    const float* bn2b = (const float*)d_in[10];
    const float* wf   = (const float*)d_in[11];
    const float* bf   = (const float*)d_in[12];
    float* out = (float*)d_out;

    const int SMEM_PREP  = (4 * H) * 4 + H * 4 + H * 129 * 4;           // 68608 B
    const int SMEM_APPLY = NSEG * H * (int)sizeof(float2) + H * (int)sizeof(float2); // 133120 B
    cudaFuncSetAttribute(k_prep,  cudaFuncAttributeMaxDynamicSharedMemorySize, SMEM_PREP);
    cudaFuncSetAttribute(k_apply, cudaFuncAttributeMaxDynamicSharedMemorySize, SMEM_APPLY);

    k_init<<<512, 256>>>(x);
    for (int l = 0; l < NLAYER; l++) {
        int uIdx = (l % 2 == 0) ? 1 : 0;
        int isLast = (l == NLAYER - 1) ? 1 : 0;
        k_prep<<<1, H, SMEM_PREP>>>(l, v1, g1, b1, bn1g, bn1b, v2, g2, b2);
        k_hist<<<512, 256>>>(uIdx);
        k_fold<<<1, H>>>(l, bn2g, bn2b);
        k_apply<<<152, 512, SMEM_APPLY>>>(uIdx, isLast, l, wf, bf, out);
    }
    (void)in_sizes; (void)n_in; (void)out_size;
}

// round 3
// speedup vs baseline: 1.0119x; 1.0119x over previous
#include <cuda_runtime.h>
#include <math_constants.h>

#define BATCH 262144
#define NLAYER 8
#define H 128
#define NSEG 129
#define BN_EPS 1e-5f
#define FLOW_EPS 1e-4f
#define INVALID 0xFFFFFFFFu

// ---------------- device scratch (no allocs allowed) ----------------
__device__ double g_sum[2];                       // sum(u), sum(u^2) of next-layer input
__device__ double g_segN[NSEG], g_segS1[NSEG], g_segS2[NSEG];
__device__ float  g_theta[H];                     // sorted kinks
__device__ __align__(16) float g_tab[NSEG * H * 2];  // [m][j]{A,B} un-folded
__device__ float2 g_ghbh[H];                      // BN2 fold factors per j
__device__ int    g_cnt[NSEG], g_off[NSEG + 1], g_cursor[NSEG], g_ptotal;
__device__ unsigned g_perm[BATCH + NSEG * 32];    // sorted (m<<18)|i, 32-aligned regions
__device__ unsigned char g_mseg[BATCH];
__device__ float g_x[2 * BATCH];
__device__ float g_sldj[BATCH];

// ---------------- init: copy x, zero sldj, stats of x1 (layer0 input) ----------------
__global__ void k_init(const float* __restrict__ x)
{
    int tid = blockIdx.x * blockDim.x + threadIdx.x;
    int stride = gridDim.x * blockDim.x;
    double s = 0.0, q = 0.0;
    for (int i = tid; i < BATCH; i += stride) {
        float2 p = ((const float2*)x)[i];
        ((float2*)g_x)[i] = p;
        g_sldj[i] = 0.f;
        s += (double)p.y;
        q += (double)p.y * (double)p.y;
    }
    for (int off = 16; off; off >>= 1) {
        s += __shfl_down_sync(0xffffffffu, s, off);
        q += __shfl_down_sync(0xffffffffu, q, off);
    }
    __shared__ double ss[32], sq[32];
    int lane = threadIdx.x & 31, w = threadIdx.x >> 5;
    if (!lane) { ss[w] = s; sq[w] = q; }
    __syncthreads();
    if (!w) {
        int nw = blockDim.x >> 5;
        s = (lane < nw) ? ss[lane] : 0.0;
        q = (lane < nw) ? sq[lane] : 0.0;
        for (int off = 16; off; off >>= 1) {
            s += __shfl_down_sync(0xffffffffu, s, off);
            q += __shfl_down_sync(0xffffffffu, q, off);
        }
        if (!lane) { atomicAdd(&g_sum[0], s); atomicAdd(&g_sum[1], q); }
    }
}

// ---------------- prep: fold BN1, sort kinks, build segment A/B table ----------------
__global__ void k_prep(int l,
    const float* __restrict__ v1, const float* __restrict__ g1, const float* __restrict__ b1,
    const float* __restrict__ bn1g, const float* __restrict__ bn1b,
    const float* __restrict__ v2, const float* __restrict__ g2, const float* __restrict__ b2)
{
    extern __shared__ float smp[];
    float* sa   = smp;
    float* sc   = sa + H;
    float* sthr = sc + H;
    float* sths = sthr + H;
    int*   sord = (int*)(sths + H);
    float* sv2  = (float*)(sord + H);   // [j][k] padded stride 129

    int k = threadIdx.x;   // 0..127
    double mu  = g_sum[0] * (1.0 / BATCH);
    double var = g_sum[1] * (1.0 / BATCH) - mu * mu;
    float meanu = (float)mu;
    float varu  = (float)(var < 0.0 ? 0.0 : var);

    float v  = v1[l * H + k];
    float w1 = g1[l * H + k] * (v / fabsf(v));
    float r  = rsqrtf(w1 * w1 * varu + BN_EPS);
    float a  = w1 * bn1g[l * H + k] * r;
    float c  = bn1b[l * H + k] - a * meanu;
    sa[k] = a; sc[k] = c;
    float th = (a != 0.f) ? (-c / a) : CUDART_INF_F;
    sthr[k] = th;
    __syncthreads();

    // rank-sort the 128 kinks (all-pairs, tie-break by index)
    int rank = 0;
    for (int j = 0; j < H; j++) {
        float tj = sthr[j];
        rank += (tj < th) || (tj == th && j < k);
    }
    sths[rank] = th;
    sord[rank] = k;
    g_theta[rank] = th;

    for (int idx = k; idx < H * H; idx += H) {
        int row = idx >> 7, col = idx & 127;
        sv2[row * 129 + col] = v2[l * H * H + idx];
    }
    __syncthreads();

    int j = k;
    float nrm = 0.f;
    for (int t = 0; t < H; t++) { float x = sv2[j * 129 + t]; nrm = fmaf(x, x, nrm); }
    float wsc = g2[l * H + j] / sqrtf(nrm);

    float A = 0.f, Bv = b2[l * H + j];
    for (int t = 0; t < H; t++) {
        float aa = sa[t], cc = sc[t];
        float w = wsc * sv2[j * 129 + t];
        if (aa < 0.f)                     { A += w * aa; Bv += w * cc; }
        else if (aa == 0.f && cc > 0.f)   { Bv += w * cc; }
    }
    g_tab[(0 * H + j) * 2]     = A;
    g_tab[(0 * H + j) * 2 + 1] = Bv;

    for (int m = 1; m <= H; m++) {
        int kk = sord[m - 1];
        float aa = sa[kk], cc = sc[kk];
        float w = wsc * sv2[j * 129 + kk];
        float sgn = (aa > 0.f) ? 1.f : ((aa < 0.f) ? -1.f : 0.f);
        A  += sgn * w * aa;
        Bv += sgn * w * cc;
        g_tab[(m * H + j) * 2]     = A;
        g_tab[(m * H + j) * 2 + 1] = Bv;
    }

    for (int i = k; i < NSEG; i += H) {
        g_segN[i] = 0.0; g_segS1[i] = 0.0; g_segS2[i] = 0.0; g_cnt[i] = 0;
    }
}

// ---------------- hist: per-sample segment + sufficient statistics + counts ----------------
__global__ void k_hist(int uIdx)
{
    __shared__ float sth[H];
    __shared__ double sN[NSEG], s1[NSEG], s2[NSEG];
    __shared__ int scnt[NSEG];
    int t = threadIdx.x;
    for (int i = t; i < H; i += blockDim.x) sth[i] = g_theta[i];
    for (int i = t; i < NSEG; i += blockDim.x) { sN[i] = 0.0; s1[i] = 0.0; s2[i] = 0.0; scnt[i] = 0; }
    __syncthreads();

    int tid = blockIdx.x * blockDim.x + t;
    int stride = gridDim.x * blockDim.x;
    for (int i = tid; i < BATCH; i += stride) {
        float2 p = ((const float2*)g_x)[i];
        float u = uIdx ? p.y : p.x;
        int m = 0;
#pragma unroll
        for (int s = 64; s >= 1; s >>= 1) { int nm = m + s; if (sth[nm - 1] < u) m = nm; }
        if (sth[H - 1] < u) m = H;   // the 7-step count saturates at 127
        g_mseg[i] = (unsigned char)m;
        atomicAdd(&sN[m], 1.0);
        atomicAdd(&s1[m], (double)u);
        atomicAdd(&s2[m], (double)u * (double)u);
        atomicAdd(&scnt[m], 1);
    }
    __syncthreads();
    for (int i = t; i < NSEG; i += blockDim.x) {
        if (scnt[i]) {
            atomicAdd(&g_segN[i],  sN[i]);
            atomicAdd(&g_segS1[i], s1[i]);
            atomicAdd(&g_segS2[i], s2[i]);
            atomicAdd(&g_cnt[i],   scnt[i]);
        }
    }
}

// ---------------- fold: BN2 fold factors (parallel), offsets, padding ----------------
__global__ void __launch_bounds__(1024) k_fold(int l,
    const float* __restrict__ bn2g, const float* __restrict__ bn2b)
{
    __shared__ double sred1[1024], sred2[1024];
    __shared__ double ssN[NSEG], ss1[NSEG], ss2[NSEG];
    __shared__ int scnt[NSEG], soff[NSEG + 1];
    int t = threadIdx.x;
    if (t < NSEG) { ssN[t] = g_segN[t]; ss1[t] = g_segS1[t]; ss2[t] = g_segS2[t]; scnt[t] = g_cnt[t]; }
    __syncthreads();

    int j = t & 127, c = t >> 7;   // 8 m-strides
    double a1 = 0.0, a2 = 0.0;
    for (int m = c; m < NSEG; m += 8) {
        float2 ab = ((const float2*)g_tab)[m * H + j];
        double N = ssN[m], S1 = ss1[m], S2 = ss2[m];
        double A = ab.x, Bv = ab.y;
        a1 += A * S1 + Bv * N;
        a2 += A * A * S2 + 2.0 * A * Bv * S1 + Bv * Bv * N;
    }
    sred1[t] = a1; sred2[t] = a2;
    __syncthreads();
    if (c == 0) {
        double m1 = 0.0, m2 = 0.0;
#pragma unroll
        for (int cc = 0; cc < 8; cc++) { m1 += sred1[cc * 128 + j]; m2 += sred2[cc * 128 + j]; }
        double mean = m1 * (1.0 / BATCH);
        double var  = m2 * (1.0 / BATCH) - mean * mean;
        if (var < 0.0) var = 0.0;
        float gh = bn2g[l * H + j] * rsqrtf((float)var + BN_EPS);
        float bh = bn2b[l * H + j] - gh * (float)mean;
        g_ghbh[j] = make_float2(gh, bh);
    }
    if (t == 0) {
        int run = 0;
        for (int m = 0; m < NSEG; m++) { soff[m] = run; run += (scnt[m] + 31) & ~31; }
        soff[NSEG] = run;
        g_ptotal = run;
    }
    if (t < NSEG) g_cursor[t] = 0;
    if (t < 2)    g_sum[t] = 0.0;
    __syncthreads();
    if (t < NSEG) {
        for (int s = soff[t] + scnt[t]; s < soff[t + 1]; s++) g_perm[s] = INVALID;
        g_off[t] = soff[t];
    }
    if (t == 0) g_off[NSEG] = soff[NSEG];
}

// ---------------- scatter: counting-sort samples into 32-aligned segment regions ----------------
#define SCAT_T 256
#define SCAT_B 512
__global__ void __launch_bounds__(SCAT_T) k_scatter()
{
    __shared__ int bcnt[NSEG], bbase[NSEG], soff[NSEG];
    int t = threadIdx.x;
    for (int i = t; i < NSEG; i += SCAT_T) { bcnt[i] = 0; soff[i] = g_off[i]; }
    __syncthreads();
    int base = blockIdx.x * SCAT_T * 2;
    int i0 = base + t, i1 = base + SCAT_T + t;
    int m0 = g_mseg[i0], m1 = g_mseg[i1];
    int r0 = atomicAdd(&bcnt[m0], 1);
    int r1 = atomicAdd(&bcnt[m1], 1);
    __syncthreads();
    for (int i = t; i < NSEG; i += SCAT_T)
        bbase[i] = bcnt[i] ? atomicAdd(&g_cursor[i], bcnt[i]) : 0;
    __syncthreads();
    g_perm[soff[m0] + bbase[m0] + r0] = ((unsigned)m0 << 18) | (unsigned)i0;
    g_perm[soff[m1] + bbase[m1] + r1] = ((unsigned)m1 << 18) | (unsigned)i1;
}

// ---------------- apply: warp-uniform segment, one sample per lane ----------------
__global__ void __launch_bounds__(1024, 1) k_apply(
    int uIdx, int isLast, int l,
    const float* __restrict__ wf, const float* __restrict__ bf,
    float* __restrict__ out)
{
    extern __shared__ float4 stab4[];          // NSEG*64 folded table rows + 64 wf float4
    float4* wf4 = stab4 + NSEG * 64;
    const float4* ghbh4 = (const float4*)g_ghbh;   // 64 float4 = (gh0,bh0,gh1,bh1)
    for (int idx = threadIdx.x; idx < NSEG * 64; idx += blockDim.x) {
        float4 tv = ((const float4*)g_tab)[idx];       // (A0,B0,A1,B1) for j pair
        float4 gb = __ldg(&ghbh4[idx & 63]);
        stab4[idx] = make_float4(gb.x * tv.x, fmaf(gb.x, tv.y, gb.y),
                                 gb.z * tv.z, fmaf(gb.z, tv.w, gb.w));
    }
    for (int jj = threadIdx.x; jj < 64; jj += blockDim.x) {
        int j0 = 2 * jj, j1 = 2 * jj + 1;
        wf4[jj] = make_float4(wf[(l * 2 + 0) * H + j0], wf[(l * 2 + 1) * H + j0],
                              wf[(l * 2 + 0) * H + j1], wf[(l * 2 + 1) * H + j1]);
    }
    __syncthreads();

    int lane = threadIdx.x & 31, wid = threadIdx.x >> 5;
    float bf0 = bf[l * 2], bf1 = bf[l * 2 + 1];
    int oIdx = 1 - uIdx;
    int P = g_ptotal;

    double accS = 0.0, accQ = 0.0;
    int gw = blockIdx.x * (blockDim.x >> 5) + wid;
    int nw = gridDim.x * (blockDim.x >> 5);

    for (int base = gw * 32; base < P; base += nw * 32) {
        unsigned pv  = g_perm[base + lane];
        unsigned pv0 = __shfl_sync(0xffffffffu, pv, 0);   // lane 0 always valid (regions 32-aligned)
        int m0 = (int)(pv0 >> 18);
        bool valid = (pv != INVALID);
        unsigned i = valid ? (pv & 0x3FFFFu) : 0u;

        float2 p = ((const float2*)g_x)[i];
        float u  = uIdx ? p.y : p.x;
        float xo = uIdx ? p.x : p.y;

        const float4* row = stab4 + m0 * 64;
        float st0a = 0.f, st1a = 0.f, st0b = 0.f, st1b = 0.f;
#pragma unroll 8
        for (int c = 0; c < 64; c += 2) {
            float4 tv = row[c];     float4 w4 = wf4[c];
            float h0 = fmaxf(fmaf(tv.x, u, tv.y), 0.f);
            float h1 = fmaxf(fmaf(tv.z, u, tv.w), 0.f);
            st0a = fmaf(w4.x, h0, fmaf(w4.z, h1, st0a));
            st1a = fmaf(w4.y, h0, fmaf(w4.w, h1, st1a));
            float4 tv2 = row[c + 1]; float4 w42 = wf4[c + 1];
            float h2 = fmaxf(fmaf(tv2.x, u, tv2.y), 0.f);
            float h3 = fmaxf(fmaf(tv2.z, u, tv2.w), 0.f);
            st0b = fmaf(w42.x, h2, fmaf(w42.z, h3, st0b));
            st1b = fmaf(w42.y, h2, fmaf(w42.w, h3, st1b));
        }
        float st0 = st0a + st0b + bf0;
        float st1 = st1a + st1b + bf1;
        float sv = tanhf(st0);
        float y  = fmaf(expf(sv), xo, st1);

        if (valid) {
            float sld = g_sldj[i] + sv;
            if (!isLast) {
                g_x[2 * i + oIdx] = y;
                g_sldj[i] = sld;
                accS += (double)y;
                accQ += (double)y * (double)y;
            } else {
                float zu = 1.f / (1.f + expf(-u));
                float zo = 1.f / (1.f + expf(-y));
                sld += logf(zu * (1.f - zu) + FLOW_EPS) + logf(zo * (1.f - zo) + FLOW_EPS);
                out[2 * i + uIdx] = zu;
                out[2 * i + oIdx] = zo;
                out[2 * BATCH + i] = sld;
            }
        }
    }

    if (!isLast) {
        for (int off = 16; off; off >>= 1) {
            accS += __shfl_down_sync(0xffffffffu, accS, off);
            accQ += __shfl_down_sync(0xffffffffu, accQ, off);
        }
        __shared__ double rs[32], rq[32];
        if (!lane) { rs[wid] = accS; rq[wid] = accQ; }
        __syncthreads();
        if (!wid) {
            int nwb = blockDim.x >> 5;
            double s = (lane < nwb) ? rs[lane] : 0.0;
            double q = (lane < nwb) ? rq[lane] : 0.0;
            for (int off = 16; off; off >>= 1) {
                s += __shfl_down_sync(0xffffffffu, s, off);
                q += __shfl_down_sync(0xffffffffu, q, off);
            }
            if (!lane) { atomicAdd(&g_sum[0], s); atomicAdd(&g_sum[1], q); }
        }
    }
}

// ---------------- host launcher ----------------
extern "C" void kernel_launch(void* const* d_in, const int* in_sizes, int n_in,
                              void* d_out, int out_size)
{
    const float* x    = (const float*)d_in[0];
    const float* v1   = (const float*)d_in[1];
    const float* g1   = (const float*)d_in[2];
    const float* b1   = (const float*)d_in[3];
    const float* bn1g = (const float*)d_in[4];
    const float* bn1b = (const float*)d_in[5];
    const float* v2   = (const float*)d_in[6];
    const float* g2   = (const float*)d_in[7];
    const float* b2   = (const float*)d_in[8];
    const float* bn2g = (const float*)d_in[9];
    const float* bn2b = (const float*)d_in[10];
    const float* wf   = (const float*)d_in[11];
    const float* bf   = (const float*)d_in[12];
    float* out = (float*)d_out;

    const int SMEM_PREP  = (4 * H) * 4 + H * 4 + H * 129 * 4;                 // 68608 B
    const int SMEM_APPLY = (NSEG * 64 + 64) * (int)sizeof(float4);            // 133120 B
    cudaFuncSetAttribute(k_prep,  cudaFuncAttributeMaxDynamicSharedMemorySize, SMEM_PREP);
    cudaFuncSetAttribute(k_apply, cudaFuncAttributeMaxDynamicSharedMemorySize, SMEM_APPLY);

    k_init<<<512, 256>>>(x);
    for (int l = 0; l < NLAYER; l++) {
        int uIdx = (l % 2 == 0) ? 1 : 0;
        int isLast = (l == NLAYER - 1) ? 1 : 0;
        k_prep<<<1, H, SMEM_PREP>>>(l, v1, g1, b1, bn1g, bn1b, v2, g2, b2);
        k_hist<<<512, 256>>>(uIdx);
        k_fold<<<1, 1024>>>(l, bn2g, bn2b);
        k_scatter<<<SCAT_B, SCAT_T>>>();
        k_apply<<<148, 1024, SMEM_APPLY>>>(uIdx, isLast, l, wf, bf, out);
    }
    (void)in_sizes; (void)n_in; (void)out_size;
}

// round 4
// speedup vs baseline: 3.4583x; 3.4177x over previous
#include <cuda_runtime.h>
#include <math_constants.h>

#define BATCH 262144
#define NLAYER 8
#define H 128
#define NSEG 129
#define BN_EPS 1e-5f
#define FLOW_EPS 1e-4f
#define INVALID 0xFFFFFFFFu
#define NREP 4

// ---------------- device scratch (no allocs allowed) ----------------
__device__ double g_sum[2];                        // sum(u), sum(u^2) of next-layer input
__device__ int    g_cntR[NREP][NSEG];              // replicated per-segment counts
__device__ double g_s1R[NREP][NSEG], g_s2R[NREP][NSEG];
__device__ int    g_cnt[NSEG];                     // combined counts (written by fold1)
__device__ double g_red1[H], g_red2[H];            // BN2 mean/sq reductions
__device__ int    g_done;                          // fold1 completion counter
__device__ float  g_theta[H];                      // sorted kinks
__device__ __align__(16) float g_tab[NSEG * H * 2];
__device__ __align__(16) float2 g_ghbh[H];         // BN2 fold factors per j
__device__ int    g_off[NSEG + 1], g_cursor[NSEG], g_ptotal;
__device__ unsigned g_perm[BATCH + NSEG * 32];
__device__ unsigned char g_mseg[BATCH];
__device__ float g_x[2 * BATCH];
__device__ float g_sldj[BATCH];

// ---------------- init: copy x, zero sldj, stats of x1 ----------------
__global__ void k_init(const float* __restrict__ x)
{
    int tid = blockIdx.x * blockDim.x + threadIdx.x;
    int stride = gridDim.x * blockDim.x;
    float kS = 0.f, cS = 0.f, kQ = 0.f, cQ = 0.f;
    for (int i = tid; i < BATCH; i += stride) {
        float2 p = ((const float2*)x)[i];
        ((float2*)g_x)[i] = p;
        g_sldj[i] = 0.f;
        float v = p.y;
        { float yk = v - cS; float tk = kS + yk; cS = (tk - kS) - yk; kS = tk; }
        float v2 = v * v;
        { float yk = v2 - cQ; float tk = kQ + yk; cQ = (tk - kQ) - yk; kQ = tk; }
    }
    double s = (double)kS, q = (double)kQ;
    for (int off = 16; off; off >>= 1) {
        s += __shfl_down_sync(0xffffffffu, s, off);
        q += __shfl_down_sync(0xffffffffu, q, off);
    }
    __shared__ double ss[32], sq[32];
    int lane = threadIdx.x & 31, w = threadIdx.x >> 5;
    if (!lane) { ss[w] = s; sq[w] = q; }
    __syncthreads();
    if (!w) {
        int nw = blockDim.x >> 5;
        s = (lane < nw) ? ss[lane] : 0.0;
        q = (lane < nw) ? sq[lane] : 0.0;
        for (int off = 16; off; off >>= 1) {
            s += __shfl_down_sync(0xffffffffu, s, off);
            q += __shfl_down_sync(0xffffffffu, q, off);
        }
        if (!lane) { atomicAdd(&g_sum[0], s); atomicAdd(&g_sum[1], q); }
    }
}

// ---------------- prep: fold BN1, sort kinks, build segment A/B table ----------------
__global__ void k_prep(int l,
    const float* __restrict__ v1, const float* __restrict__ g1, const float* __restrict__ b1,
    const float* __restrict__ bn1g, const float* __restrict__ bn1b,
    const float* __restrict__ v2, const float* __restrict__ g2, const float* __restrict__ b2)
{
    extern __shared__ float smp[];
    float* sa   = smp;
    float* sc   = sa + H;
    float* sthr = sc + H;
    int*   sord = (int*)(sthr + H);
    float* sv2  = (float*)(sord + H);   // [j][k] padded stride 129

    int t = threadIdx.x;   // 0..255
    if (t < H) {
        int k = t;
        double mu  = g_sum[0] * (1.0 / BATCH);
        double var = g_sum[1] * (1.0 / BATCH) - mu * mu;
        float meanu = (float)mu;
        float varu  = (float)(var < 0.0 ? 0.0 : var);
        float v  = v1[l * H + k];
        float w1 = g1[l * H + k] * (v / fabsf(v));
        float r  = rsqrtf(w1 * w1 * varu + BN_EPS);
        float a  = w1 * bn1g[l * H + k] * r;
        float c  = bn1b[l * H + k] - a * meanu;
        sa[k] = a; sc[k] = c;
        sthr[k] = (a != 0.f) ? (-c / a) : CUDART_INF_F;
    }
    __syncthreads();
    if (t < H) {
        int k = t;
        float th = sthr[k];
        int rank = 0;
        for (int j = 0; j < H; j++) {
            float tj = sthr[j];
            rank += (tj < th) || (tj == th && j < k);
        }
        sord[rank] = k;
        g_theta[rank] = th;
    }
    // overlap: all 256 threads stream v2 into padded smem while ranks compute
    for (int idx = t; idx < H * H; idx += 256) {
        int row = idx >> 7, col = idx & 127;
        sv2[row * 129 + col] = v2[l * H * H + idx];
    }
    __syncthreads();

    if (t < H) {
        int j = t;
        float nrm = 0.f;
        for (int tt = 0; tt < H; tt++) { float x = sv2[j * 129 + tt]; nrm = fmaf(x, x, nrm); }
        float wsc = g2[l * H + j] / sqrtf(nrm);

        float A = 0.f, Bv = b2[l * H + j];
        for (int tt = 0; tt < H; tt++) {
            float aa = sa[tt], cc = sc[tt];
            float w = wsc * sv2[j * 129 + tt];
            if (aa < 0.f)                     { A += w * aa; Bv += w * cc; }
            else if (aa == 0.f && cc > 0.f)   { Bv += w * cc; }
        }
        g_tab[(0 * H + j) * 2]     = A;
        g_tab[(0 * H + j) * 2 + 1] = Bv;

        for (int m = 1; m <= H; m++) {
            int kk = sord[m - 1];
            float aa = sa[kk], cc = sc[kk];
            float w = wsc * sv2[j * 129 + kk];
            float sgn = (aa > 0.f) ? 1.f : ((aa < 0.f) ? -1.f : 0.f);
            A  += sgn * w * aa;
            Bv += sgn * w * cc;
            g_tab[(m * H + j) * 2]     = A;
            g_tab[(m * H + j) * 2 + 1] = Bv;
        }
    }
}

// ---------------- hist: fp32/int smem atomics; warp-reduced hot tails ----------------
#define HIST_B 148
#define HIST_T 512
__global__ void __launch_bounds__(HIST_T) k_hist(int uIdx)
{
    __shared__ float sth[H];
    __shared__ int   scnt[NSEG];
    __shared__ float ss1[NSEG], ss2[NSEG];
    int t = threadIdx.x;
    if (t < H) sth[t] = g_theta[t];
    for (int i = t; i < NSEG; i += HIST_T) { scnt[i] = 0; ss1[i] = 0.f; ss2[i] = 0.f; }
    __syncthreads();

    int lane = t & 31;
    int tid = blockIdx.x * HIST_T + t;
    int stride = gridDim.x * HIST_T;
    // BATCH and stride are multiples of 32 -> warp-uniform trip count (ballots safe)
    for (int i = tid; i < BATCH; i += stride) {
        float2 p = ((const float2*)g_x)[i];
        float u = uIdx ? p.y : p.x;
        int m = 0;
#pragma unroll
        for (int s = 64; s >= 1; s >>= 1) { int nm = m + s; if (sth[nm - 1] < u) m = nm; }
        if (sth[H - 1] < u) m = H;   // 7-step count saturates at 127
        g_mseg[i] = (unsigned char)m;

        bool lo = (m == 0), hi = (m == H);
        float u2 = u * u;
        float s1l = lo ? u : 0.f, s2l = lo ? u2 : 0.f;
        float s1h = hi ? u : 0.f, s2h = hi ? u2 : 0.f;
#pragma unroll
        for (int off = 16; off; off >>= 1) {
            s1l += __shfl_xor_sync(0xffffffffu, s1l, off);
            s2l += __shfl_xor_sync(0xffffffffu, s2l, off);
            s1h += __shfl_xor_sync(0xffffffffu, s1h, off);
            s2h += __shfl_xor_sync(0xffffffffu, s2h, off);
        }
        unsigned blo = __ballot_sync(0xffffffffu, lo);
        unsigned bhi = __ballot_sync(0xffffffffu, hi);
        if (lane == 0) {
            if (blo) { atomicAdd(&scnt[0], __popc(blo)); atomicAdd(&ss1[0], s1l); atomicAdd(&ss2[0], s2l); }
            if (bhi) { atomicAdd(&scnt[H], __popc(bhi)); atomicAdd(&ss1[H], s1h); atomicAdd(&ss2[H], s2h); }
        }
        if (!lo && !hi) {
            atomicAdd(&scnt[m], 1);
            atomicAdd(&ss1[m], u);
            atomicAdd(&ss2[m], u2);
        }
    }
    __syncthreads();
    int r = blockIdx.x & (NREP - 1);
    for (int i = t; i < NSEG; i += HIST_T) {
        if (scnt[i]) {
            atomicAdd(&g_cntR[r][i], scnt[i]);
            atomicAdd(&g_s1R[r][i], (double)ss1[i]);
            atomicAdd(&g_s2R[r][i], (double)ss2[i]);
        }
    }
}

// ---------------- fold1: per-segment BN2 partials (129 blocks) + last-block epilogue ----------------
__global__ void __launch_bounds__(H) k_fold1(int l,
    const float* __restrict__ bn2g, const float* __restrict__ bn2b)
{
    int m = blockIdx.x, j = threadIdx.x;
    __shared__ double shN, shS1, shS2;
    if (j == 0) {
        int c = 0; double s1 = 0.0, s2 = 0.0;
#pragma unroll
        for (int r = 0; r < NREP; r++) {
            c  += g_cntR[r][m];
            s1 += g_s1R[r][m];
            s2 += g_s2R[r][m];
        }
        shN = (double)c; shS1 = s1; shS2 = s2;
        g_cnt[m] = c;
    }
    __syncthreads();
    double N = shN, S1 = shS1, S2 = shS2;
    float2 ab = ((const float2*)g_tab)[m * H + j];
    double A = (double)ab.x, Bv = (double)ab.y;
    atomicAdd(&g_red1[j], A * S1 + Bv * N);
    atomicAdd(&g_red2[j], A * A * S2 + 2.0 * A * Bv * S1 + Bv * Bv * N);

    __threadfence();
    __shared__ int lastBlk;
    if (j == 0) lastBlk = (atomicAdd(&g_done, 1) == NSEG - 1) ? 1 : 0;
    __syncthreads();
    if (!lastBlk) return;
    __threadfence();

    // ---- epilogue (one block, 128 threads) ----
    __shared__ int ecnt[NSEG], eoff[NSEG + 1];
    ecnt[j] = g_cnt[j];
    if (j == 0) ecnt[H] = g_cnt[H];
    __syncthreads();
    if (j == 0) {
        int run = 0;
        for (int s = 0; s < NSEG; s++) { eoff[s] = run; run += (ecnt[s] + 31) & ~31; }
        eoff[NSEG] = run;
        g_ptotal = run;
        g_off[H] = eoff[H]; g_off[NSEG] = eoff[NSEG];
        g_cursor[H] = 0;
        g_done = 0;
        g_sum[0] = 0.0; g_sum[1] = 0.0;
    }
    __syncthreads();
    g_off[j] = eoff[j];
    g_cursor[j] = 0;
    // pad alignment slack with INVALID
    {
        int s = j;
        for (int p = eoff[s] + ecnt[s]; p < eoff[s + 1]; p++) g_perm[p] = INVALID;
        if (j == 0) {
            int s2 = H;
            for (int p = eoff[s2] + ecnt[s2]; p < eoff[s2 + 1]; p++) g_perm[p] = INVALID;
        }
    }
    // BN2 fold factors
    {
        double mean = g_red1[j] * (1.0 / BATCH);
        double var  = g_red2[j] * (1.0 / BATCH) - mean * mean;
        if (var < 0.0) var = 0.0;
        float gh = bn2g[l * H + j] * rsqrtf((float)var + BN_EPS);
        float bh = bn2b[l * H + j] - gh * (float)mean;
        g_ghbh[j] = make_float2(gh, bh);
        g_red1[j] = 0.0; g_red2[j] = 0.0;
    }
    // zero replicated stats for next layer
    for (int idx = j; idx < NREP * NSEG; idx += H) {
        ((int*)g_cntR)[idx] = 0;
        ((double*)g_s1R)[idx] = 0.0;
        ((double*)g_s2R)[idx] = 0.0;
    }
}

// ---------------- scatter: counting-sort samples into 32-aligned segment regions ----------------
#define SCAT_T 256
#define SCAT_B 512
__global__ void __launch_bounds__(SCAT_T) k_scatter()
{
    __shared__ int bcnt[NSEG], bbase[NSEG], soff[NSEG];
    int t = threadIdx.x;
    for (int i = t; i < NSEG; i += SCAT_T) { bcnt[i] = 0; soff[i] = g_off[i]; }
    __syncthreads();
    int base = blockIdx.x * SCAT_T * 2;
    int i0 = base + t, i1 = base + SCAT_T + t;
    int m0 = g_mseg[i0], m1 = g_mseg[i1];
    int r0 = atomicAdd(&bcnt[m0], 1);
    int r1 = atomicAdd(&bcnt[m1], 1);
    __syncthreads();
    for (int i = t; i < NSEG; i += SCAT_T)
        bbase[i] = bcnt[i] ? atomicAdd(&g_cursor[i], bcnt[i]) : 0;
    __syncthreads();
    g_perm[soff[m0] + bbase[m0] + r0] = ((unsigned)m0 << 18) | (unsigned)i0;
    g_perm[soff[m1] + bbase[m1] + r1] = ((unsigned)m1 << 18) | (unsigned)i1;
}

// ---------------- apply: warp-uniform segment, one sample per lane ----------------
__global__ void __launch_bounds__(1024, 1) k_apply(
    int uIdx, int isLast, int l,
    const float* __restrict__ wf, const float* __restrict__ bf,
    float* __restrict__ out)
{
    extern __shared__ float4 stab4[];          // NSEG*64 folded rows + 64 wf float4
    float4* wf4 = stab4 + NSEG * 64;
    const float4* ghbh4 = (const float4*)g_ghbh;   // (gh0,bh0,gh1,bh1) per j-pair
    for (int idx = threadIdx.x; idx < NSEG * 64; idx += blockDim.x) {
        float4 tv = ((const float4*)g_tab)[idx];
        float4 gb = __ldg(&ghbh4[idx & 63]);
        stab4[idx] = make_float4(gb.x * tv.x, fmaf(gb.x, tv.y, gb.y),
                                 gb.z * tv.z, fmaf(gb.z, tv.w, gb.w));
    }
    for (int jj = threadIdx.x; jj < 64; jj += blockDim.x) {
        int j0 = 2 * jj, j1 = 2 * jj + 1;
        wf4[jj] = make_float4(wf[(l * 2 + 0) * H + j0], wf[(l * 2 + 1) * H + j0],
                              wf[(l * 2 + 0) * H + j1], wf[(l * 2 + 1) * H + j1]);
    }
    __syncthreads();

    int lane = threadIdx.x & 31, wid = threadIdx.x >> 5;
    float bf0 = bf[l * 2], bf1 = bf[l * 2 + 1];
    int oIdx = 1 - uIdx;
    int P = g_ptotal;

    float kS = 0.f, cS = 0.f, kQ = 0.f, cQ = 0.f;   // Kahan fp32 accumulators
    int gw = blockIdx.x * (blockDim.x >> 5) + wid;
    int nw = gridDim.x * (blockDim.x >> 5);

    for (int base = gw * 32; base < P; base += nw * 32) {
        unsigned pv  = g_perm[base + lane];
        unsigned pv0 = __shfl_sync(0xffffffffu, pv, 0);   // lane 0 valid (32-aligned regions)
        int m0 = (int)(pv0 >> 18);
        bool valid = (pv != INVALID);
        unsigned i = valid ? (pv & 0x3FFFFu) : 0u;

        float2 p = ((const float2*)g_x)[i];
        float u  = uIdx ? p.y : p.x;
        float xo = uIdx ? p.x : p.y;

        const float4* row = stab4 + m0 * 64;
        float st0a = 0.f, st1a = 0.f, st0b = 0.f, st1b = 0.f;
#pragma unroll 8
        for (int c = 0; c < 64; c += 2) {
            float4 tv = row[c];     float4 w4 = wf4[c];
            float h0 = fmaxf(fmaf(tv.x, u, tv.y), 0.f);
            float h1 = fmaxf(fmaf(tv.z, u, tv.w), 0.f);
            st0a = fmaf(w4.x, h0, fmaf(w4.z, h1, st0a));
            st1a = fmaf(w4.y, h0, fmaf(w4.w, h1, st1a));
            float4 tv2 = row[c + 1]; float4 w42 = wf4[c + 1];
            float h2 = fmaxf(fmaf(tv2.x, u, tv2.y), 0.f);
            float h3 = fmaxf(fmaf(tv2.z, u, tv2.w), 0.f);
            st0b = fmaf(w42.x, h2, fmaf(w42.z, h3, st0b));
            st1b = fmaf(w42.y, h2, fmaf(w42.w, h3, st1b));
        }
        float st0 = st0a + st0b + bf0;
        float st1 = st1a + st1b + bf1;
        float e2  = __expf(2.f * st0);
        float sv  = 1.f - 2.f * __fdividef(1.f, e2 + 1.f);   // tanh(st0)
        float y   = fmaf(__expf(sv), xo, st1);

        if (valid) {
            float sld = g_sldj[i] + sv;
            if (!isLast) {
                g_x[2 * i + oIdx] = y;
                g_sldj[i] = sld;
                { float yk = y - cS;  float tk = kS + yk; cS = (tk - kS) - yk; kS = tk; }
                float yy = y * y;
                { float yk = yy - cQ; float tk = kQ + yk; cQ = (tk - kQ) - yk; kQ = tk; }
            } else {
                float zu = __fdividef(1.f, 1.f + __expf(-u));
                float zo = __fdividef(1.f, 1.f + __expf(-y));
                sld += __logf(zu * (1.f - zu) + FLOW_EPS) + __logf(zo * (1.f - zo) + FLOW_EPS);
                out[2 * i + uIdx] = zu;
                out[2 * i + oIdx] = zo;
                out[2 * BATCH + i] = sld;
            }
        }
    }

    if (!isLast) {
        double s = (double)kS, q = (double)kQ;
        for (int off = 16; off; off >>= 1) {
            s += __shfl_down_sync(0xffffffffu, s, off);
            q += __shfl_down_sync(0xffffffffu, q, off);
        }
        __shared__ double rs[32], rq[32];
        if (!lane) { rs[wid] = s; rq[wid] = q; }
        __syncthreads();
        if (!wid) {
            int nwb = blockDim.x >> 5;
            s = (lane < nwb) ? rs[lane] : 0.0;
            q = (lane < nwb) ? rq[lane] : 0.0;
            for (int off = 16; off; off >>= 1) {
                s += __shfl_down_sync(0xffffffffu, s, off);
                q += __shfl_down_sync(0xffffffffu, q, off);
            }
            if (!lane) { atomicAdd(&g_sum[0], s); atomicAdd(&g_sum[1], q); }
        }
    }
}

// ---------------- host launcher ----------------
extern "C" void kernel_launch(void* const* d_in, const int* in_sizes, int n_in,
                              void* d_out, int out_size)
{
    const float* x    = (const float*)d_in[0];
    const float* v1   = (const float*)d_in[1];
    const float* g1   = (const float*)d_in[2];
    const float* b1   = (const float*)d_in[3];
    const float* bn1g = (const float*)d_in[4];
    const float* bn1b = (const float*)d_in[5];
    const float* v2   = (const float*)d_in[6];
    const float* g2   = (const float*)d_in[7];
    const float* b2   = (const float*)d_in[8];
    const float* bn2g = (const float*)d_in[9];
    const float* bn2b = (const float*)d_in[10];
    const float* wf   = (const float*)d_in[11];
    const float* bf   = (const float*)d_in[12];
    float* out = (float*)d_out;

    const int SMEM_PREP  = (3 * H) * 4 + H * 4 + H * 129 * 4;                 // ~68 KB
    const int SMEM_APPLY = (NSEG * 64 + 64) * (int)sizeof(float4);            // 133120 B
    cudaFuncSetAttribute(k_prep,  cudaFuncAttributeMaxDynamicSharedMemorySize, SMEM_PREP);
    cudaFuncSetAttribute(k_apply, cudaFuncAttributeMaxDynamicSharedMemorySize, SMEM_APPLY);

    k_init<<<512, 256>>>(x);
    for (int l = 0; l < NLAYER; l++) {
        int uIdx = (l % 2 == 0) ? 1 : 0;
        int isLast = (l == NLAYER - 1) ? 1 : 0;
        k_prep<<<1, 256, SMEM_PREP>>>(l, v1, g1, b1, bn1g, bn1b, v2, g2, b2);
        k_hist<<<HIST_B, HIST_T>>>(uIdx);
        k_fold1<<<NSEG, H>>>(l, bn2g, bn2b);
        k_scatter<<<SCAT_B, SCAT_T>>>();
        k_apply<<<148, 1024, SMEM_APPLY>>>(uIdx, isLast, l, wf, bf, out);
    }
    (void)in_sizes; (void)n_in; (void)out_size;
}

// round 5
// speedup vs baseline: 3.7773x; 1.0923x over previous
#include <cuda_runtime.h>
#include <math_constants.h>

#define BATCH 262144
#define NLAYER 8
#define H 128
#define NSEG 129
#define BN_EPS 1e-5f
#define FLOW_EPS 1e-4f
#define INVALID 0xFFFFFFFFu
#define NREP 4

// ---------------- device scratch (no allocs allowed) ----------------
__device__ double g_sum[2];                        // sum(u), sum(u^2) of next-layer input
__device__ int    g_cntR[NREP][NSEG];              // replicated per-segment counts
__device__ double g_s1R[NREP][NSEG], g_s2R[NREP][NSEG];
__device__ float  g_theta[H];                      // sorted kinks
__device__ __align__(16) float g_tab[NSEG * H * 2];
__device__ __align__(16) float2 g_ghbh[H];         // BN2 fold factors per j
__device__ int    g_off[NSEG + 1], g_cursor[NSEG], g_ptotal;
__device__ unsigned g_perm[BATCH + NSEG * 32];
__device__ unsigned char g_mseg[BATCH];
__device__ float g_x[2 * BATCH];
__device__ float g_sldj[BATCH];

// ---------------- init: copy x, zero sldj, stats of x1 ----------------
__global__ void k_init(const float* __restrict__ x)
{
    int tid = blockIdx.x * blockDim.x + threadIdx.x;
    int stride = gridDim.x * blockDim.x;
    float kS = 0.f, cS = 0.f, kQ = 0.f, cQ = 0.f;
    for (int i = tid; i < BATCH; i += stride) {
        float2 p = ((const float2*)x)[i];
        ((float2*)g_x)[i] = p;
        g_sldj[i] = 0.f;
        float v = p.y;
        { float yk = v - cS; float tk = kS + yk; cS = (tk - kS) - yk; kS = tk; }
        float v2 = v * v;
        { float yk = v2 - cQ; float tk = kQ + yk; cQ = (tk - kQ) - yk; kQ = tk; }
    }
    double s = (double)kS, q = (double)kQ;
    for (int off = 16; off; off >>= 1) {
        s += __shfl_down_sync(0xffffffffu, s, off);
        q += __shfl_down_sync(0xffffffffu, q, off);
    }
    __shared__ double ss[32], sq[32];
    int lane = threadIdx.x & 31, w = threadIdx.x >> 5;
    if (!lane) { ss[w] = s; sq[w] = q; }
    __syncthreads();
    if (!w) {
        int nw = blockDim.x >> 5;
        s = (lane < nw) ? ss[lane] : 0.0;
        q = (lane < nw) ? sq[lane] : 0.0;
        for (int off = 16; off; off >>= 1) {
            s += __shfl_down_sync(0xffffffffu, s, off);
            q += __shfl_down_sync(0xffffffffu, q, off);
        }
        if (!lane) { atomicAdd(&g_sum[0], s); atomicAdd(&g_sum[1], q); }
    }
}

// ---------------- prep: fold BN1, sort kinks, build segment A/B table ----------------
__global__ void k_prep(int l,
    const float* __restrict__ v1, const float* __restrict__ g1, const float* __restrict__ b1,
    const float* __restrict__ bn1g, const float* __restrict__ bn1b,
    const float* __restrict__ v2, const float* __restrict__ g2, const float* __restrict__ b2)
{
    extern __shared__ float smp[];
    float* sa   = smp;
    float* sc   = sa + H;
    float* sthr = sc + H;
    int*   sord = (int*)(sthr + H);
    float* sv2  = (float*)(sord + H);   // [j][k] padded stride 129

    int t = threadIdx.x;   // 0..255
    if (t < H) {
        int k = t;
        double mu  = g_sum[0] * (1.0 / BATCH);
        double var = g_sum[1] * (1.0 / BATCH) - mu * mu;
        float meanu = (float)mu;
        float varu  = (float)(var < 0.0 ? 0.0 : var);
        float v  = v1[l * H + k];
        float w1 = g1[l * H + k] * (v / fabsf(v));
        float r  = rsqrtf(w1 * w1 * varu + BN_EPS);
        float a  = w1 * bn1g[l * H + k] * r;
        float c  = bn1b[l * H + k] - a * meanu;
        sa[k] = a; sc[k] = c;
        sthr[k] = (a != 0.f) ? (-c / a) : CUDART_INF_F;
    }
    __syncthreads();
    if (t < H) {
        int k = t;
        float th = sthr[k];
        int rank = 0;
        for (int j = 0; j < H; j++) {
            float tj = sthr[j];
            rank += (tj < th) || (tj == th && j < k);
        }
        sord[rank] = k;
        g_theta[rank] = th;
    }
    // overlap: all 256 threads stream v2 into padded smem while ranks compute
    for (int idx = t; idx < H * H; idx += 256) {
        int row = idx >> 7, col = idx & 127;
        sv2[row * 129 + col] = v2[l * H * H + idx];
    }
    __syncthreads();

    if (t < H) {
        int j = t;
        float nrm = 0.f;
        for (int tt = 0; tt < H; tt++) { float x = sv2[j * 129 + tt]; nrm = fmaf(x, x, nrm); }
        float wsc = g2[l * H + j] / sqrtf(nrm);

        float A = 0.f, Bv = b2[l * H + j];
        for (int tt = 0; tt < H; tt++) {
            float aa = sa[tt], cc = sc[tt];
            float w = wsc * sv2[j * 129 + tt];
            if (aa < 0.f)                     { A += w * aa; Bv += w * cc; }
            else if (aa == 0.f && cc > 0.f)   { Bv += w * cc; }
        }
        g_tab[(0 * H + j) * 2]     = A;
        g_tab[(0 * H + j) * 2 + 1] = Bv;

        for (int m = 1; m <= H; m++) {
            int kk = sord[m - 1];
            float aa = sa[kk], cc = sc[kk];
            float w = wsc * sv2[j * 129 + kk];
            float sgn = (aa > 0.f) ? 1.f : ((aa < 0.f) ? -1.f : 0.f);
            A  += sgn * w * aa;
            Bv += sgn * w * cc;
            g_tab[(m * H + j) * 2]     = A;
            g_tab[(m * H + j) * 2 + 1] = Bv;
        }
    }
}

// ---------------- hist: fp32/int smem atomics; warp-reduced hot tails ----------------
#define HIST_B 148
#define HIST_T 512
__global__ void __launch_bounds__(HIST_T) k_hist(int uIdx)
{
    __shared__ float sth[H];
    __shared__ int   scnt[NSEG];
    __shared__ float ss1[NSEG], ss2[NSEG];
    int t = threadIdx.x;
    if (t < H) sth[t] = g_theta[t];
    for (int i = t; i < NSEG; i += HIST_T) { scnt[i] = 0; ss1[i] = 0.f; ss2[i] = 0.f; }
    __syncthreads();

    int lane = t & 31;
    int tid = blockIdx.x * HIST_T + t;
    int stride = gridDim.x * HIST_T;
    // BATCH and stride are multiples of 32 -> warp-uniform trip count (ballots safe)
    for (int i = tid; i < BATCH; i += stride) {
        float2 p = ((const float2*)g_x)[i];
        float u = uIdx ? p.y : p.x;
        int m = 0;
#pragma unroll
        for (int s = 64; s >= 1; s >>= 1) { int nm = m + s; if (sth[nm - 1] < u) m = nm; }
        if (sth[H - 1] < u) m = H;   // 7-step count saturates at 127
        g_mseg[i] = (unsigned char)m;

        bool lo = (m == 0), hi = (m == H);
        float u2 = u * u;
        float s1l = lo ? u : 0.f, s2l = lo ? u2 : 0.f;
        float s1h = hi ? u : 0.f, s2h = hi ? u2 : 0.f;
#pragma unroll
        for (int off = 16; off; off >>= 1) {
            s1l += __shfl_xor_sync(0xffffffffu, s1l, off);
            s2l += __shfl_xor_sync(0xffffffffu, s2l, off);
            s1h += __shfl_xor_sync(0xffffffffu, s1h, off);
            s2h += __shfl_xor_sync(0xffffffffu, s2h, off);
        }
        unsigned blo = __ballot_sync(0xffffffffu, lo);
        unsigned bhi = __ballot_sync(0xffffffffu, hi);
        if (lane == 0) {
            if (blo) { atomicAdd(&scnt[0], __popc(blo)); atomicAdd(&ss1[0], s1l); atomicAdd(&ss2[0], s2l); }
            if (bhi) { atomicAdd(&scnt[H], __popc(bhi)); atomicAdd(&ss1[H], s1h); atomicAdd(&ss2[H], s2h); }
        }
        if (!lo && !hi) {
            atomicAdd(&scnt[m], 1);
            atomicAdd(&ss1[m], u);
            atomicAdd(&ss2[m], u2);
        }
    }
    __syncthreads();
    int r = blockIdx.x & (NREP - 1);
    for (int i = t; i < NSEG; i += HIST_T) {
        if (scnt[i]) {
            atomicAdd(&g_cntR[r][i], scnt[i]);
            atomicAdd(&g_s1R[r][i], (double)ss1[i]);
            atomicAdd(&g_s2R[r][i], (double)ss2[i]);
        }
    }
}

// ---------------- fold: blocks 0..127 = BN2 factors per j (no atomics);
//                   block 128 = offsets/padding/cursors/g_sum reset ----------------
__global__ void __launch_bounds__(H) k_fold(int l,
    const float* __restrict__ bn2g, const float* __restrict__ bn2b)
{
    int t = threadIdx.x;
    if (blockIdx.x < H) {
        int j = blockIdx.x;
        double a1 = 0.0, a2 = 0.0;
        for (int m = t; m < NSEG; m += H) {   // thread t: m=t; thread 0 also m=128
            int c = 0; double S1 = 0.0, S2 = 0.0;
#pragma unroll
            for (int r = 0; r < NREP; r++) {
                c  += g_cntR[r][m];
                S1 += g_s1R[r][m];
                S2 += g_s2R[r][m];
            }
            float2 ab = ((const float2*)g_tab)[m * H + j];
            double A = (double)ab.x, Bv = (double)ab.y, N = (double)c;
            a1 += A * S1 + Bv * N;
            a2 += A * A * S2 + 2.0 * A * Bv * S1 + Bv * Bv * N;
        }
        __shared__ double r1[H], r2[H];
        r1[t] = a1; r2[t] = a2;
        __syncthreads();
#pragma unroll
        for (int off = 64; off; off >>= 1) {
            if (t < off) { r1[t] += r1[t + off]; r2[t] += r2[t + off]; }
            __syncthreads();
        }
        if (t == 0) {
            double mean = r1[0] * (1.0 / BATCH);
            double var  = r2[0] * (1.0 / BATCH) - mean * mean;
            if (var < 0.0) var = 0.0;
            float gh = bn2g[l * H + j] * rsqrtf((float)var + BN_EPS);
            float bh = bn2b[l * H + j] - gh * (float)mean;
            g_ghbh[j] = make_float2(gh, bh);
        }
    } else {
        // offsets block
        __shared__ int ecnt[NSEG], eoff[NSEG + 1];
        for (int m = t; m < NSEG; m += H) {
            int c = 0;
#pragma unroll
            for (int r = 0; r < NREP; r++) c += g_cntR[r][m];
            ecnt[m] = c;
        }
        __syncthreads();
        if (t == 0) {
            int run = 0;
            for (int s = 0; s < NSEG; s++) { eoff[s] = run; run += (ecnt[s] + 31) & ~31; }
            eoff[NSEG] = run;
            g_ptotal = run;
            g_off[NSEG] = run;
            g_sum[0] = 0.0; g_sum[1] = 0.0;
        }
        __syncthreads();
        for (int m = t; m < NSEG; m += H) {
            g_off[m] = eoff[m];
            g_cursor[m] = 0;
            for (int p = eoff[m] + ecnt[m]; p < eoff[m + 1]; p++) g_perm[p] = INVALID;
        }
    }
}

// ---------------- scatter: counting-sort samples into 32-aligned segment regions ----------------
#define SCAT_T 256
#define SCAT_B 512
__global__ void __launch_bounds__(SCAT_T) k_scatter()
{
    __shared__ int bcnt[NSEG], bbase[NSEG], soff[NSEG];
    int t = threadIdx.x;
    for (int i = t; i < NSEG; i += SCAT_T) { bcnt[i] = 0; soff[i] = g_off[i]; }
    __syncthreads();
    int base = blockIdx.x * SCAT_T * 2;
    int i0 = base + t, i1 = base + SCAT_T + t;
    int m0 = g_mseg[i0], m1 = g_mseg[i1];
    int r0 = atomicAdd(&bcnt[m0], 1);
    int r1 = atomicAdd(&bcnt[m1], 1);
    __syncthreads();
    for (int i = t; i < NSEG; i += SCAT_T)
        bbase[i] = bcnt[i] ? atomicAdd(&g_cursor[i], bcnt[i]) : 0;
    __syncthreads();
    g_perm[soff[m0] + bbase[m0] + r0] = ((unsigned)m0 << 18) | (unsigned)i0;
    g_perm[soff[m1] + bbase[m1] + r1] = ((unsigned)m1 << 18) | (unsigned)i1;
}

// ---------------- apply: warp-uniform segment, one sample per lane ----------------
__global__ void __launch_bounds__(1024, 1) k_apply(
    int uIdx, int isLast, int l,
    const float* __restrict__ wf, const float* __restrict__ bf,
    float* __restrict__ out)
{
    extern __shared__ float4 stab4[];          // NSEG*64 folded rows + 64 wf float4
    float4* wf4 = stab4 + NSEG * 64;
    const float4* ghbh4 = (const float4*)g_ghbh;   // (gh0,bh0,gh1,bh1) per j-pair
    for (int idx = threadIdx.x; idx < NSEG * 64; idx += blockDim.x) {
        float4 tv = ((const float4*)g_tab)[idx];
        float4 gb = __ldg(&ghbh4[idx & 63]);
        stab4[idx] = make_float4(gb.x * tv.x, fmaf(gb.x, tv.y, gb.y),
                                 gb.z * tv.z, fmaf(gb.z, tv.w, gb.w));
    }
    for (int jj = threadIdx.x; jj < 64; jj += blockDim.x) {
        int j0 = 2 * jj, j1 = 2 * jj + 1;
        wf4[jj] = make_float4(wf[(l * 2 + 0) * H + j0], wf[(l * 2 + 1) * H + j0],
                              wf[(l * 2 + 0) * H + j1], wf[(l * 2 + 1) * H + j1]);
    }
    // block 0: zero the replicated seg-stat scratch for the NEXT hist (fold already consumed it)
    if (blockIdx.x == 0) {
        for (int idx = threadIdx.x; idx < NREP * NSEG; idx += blockDim.x) {
            ((int*)g_cntR)[idx] = 0;
            ((double*)g_s1R)[idx] = 0.0;
            ((double*)g_s2R)[idx] = 0.0;
        }
    }
    __syncthreads();

    int lane = threadIdx.x & 31, wid = threadIdx.x >> 5;
    float bf0 = bf[l * 2], bf1 = bf[l * 2 + 1];
    int oIdx = 1 - uIdx;
    int P = g_ptotal;

    float kS = 0.f, cS = 0.f, kQ = 0.f, cQ = 0.f;   // Kahan fp32 accumulators
    int gw = blockIdx.x * (blockDim.x >> 5) + wid;
    int nw = gridDim.x * (blockDim.x >> 5);

    for (int base = gw * 32; base < P; base += nw * 32) {
        unsigned pv  = g_perm[base + lane];
        unsigned pv0 = __shfl_sync(0xffffffffu, pv, 0);   // lane 0 valid (32-aligned regions)
        int m0 = (int)(pv0 >> 18);
        bool valid = (pv != INVALID);
        unsigned i = valid ? (pv & 0x3FFFFu) : 0u;

        float2 p = ((const float2*)g_x)[i];
        float u  = uIdx ? p.y : p.x;
        float xo = uIdx ? p.x : p.y;

        const float4* row = stab4 + m0 * 64;
        float st0a = 0.f, st1a = 0.f, st0b = 0.f, st1b = 0.f;
#pragma unroll 8
        for (int c = 0; c < 64; c += 2) {
            float4 tv = row[c];     float4 w4 = wf4[c];
            float h0 = fmaxf(fmaf(tv.x, u, tv.y), 0.f);
            float h1 = fmaxf(fmaf(tv.z, u, tv.w), 0.f);
            st0a = fmaf(w4.x, h0, fmaf(w4.z, h1, st0a));
            st1a = fmaf(w4.y, h0, fmaf(w4.w, h1, st1a));
            float4 tv2 = row[c + 1]; float4 w42 = wf4[c + 1];
            float h2 = fmaxf(fmaf(tv2.x, u, tv2.y), 0.f);
            float h3 = fmaxf(fmaf(tv2.z, u, tv2.w), 0.f);
            st0b = fmaf(w42.x, h2, fmaf(w42.z, h3, st0b));
            st1b = fmaf(w42.y, h2, fmaf(w42.w, h3, st1b));
        }
        float st0 = st0a + st0b + bf0;
        float st1 = st1a + st1b + bf1;
        float e2  = __expf(2.f * st0);
        float sv  = 1.f - 2.f * __fdividef(1.f, e2 + 1.f);   // tanh(st0)
        float y   = fmaf(__expf(sv), xo, st1);

        if (valid) {
            float sld = g_sldj[i] + sv;
            if (!isLast) {
                g_x[2 * i + oIdx] = y;
                g_sldj[i] = sld;
                { float yk = y - cS;  float tk = kS + yk; cS = (tk - kS) - yk; kS = tk; }
                float yy = y * y;
                { float yk = yy - cQ; float tk = kQ + yk; cQ = (tk - kQ) - yk; kQ = tk; }
            } else {
                float zu = __fdividef(1.f, 1.f + __expf(-u));
                float zo = __fdividef(1.f, 1.f + __expf(-y));
                sld += __logf(zu * (1.f - zu) + FLOW_EPS) + __logf(zo * (1.f - zo) + FLOW_EPS);
                out[2 * i + uIdx] = zu;
                out[2 * i + oIdx] = zo;
                out[2 * BATCH + i] = sld;
            }
        }
    }

    if (!isLast) {
        double s = (double)kS, q = (double)kQ;
        for (int off = 16; off; off >>= 1) {
            s += __shfl_down_sync(0xffffffffu, s, off);
            q += __shfl_down_sync(0xffffffffu, q, off);
        }
        __shared__ double rs[32], rq[32];
        if (!lane) { rs[wid] = s; rq[wid] = q; }
        __syncthreads();
        if (!wid) {
            int nwb = blockDim.x >> 5;
            s = (lane < nwb) ? rs[lane] : 0.0;
            q = (lane < nwb) ? rq[lane] : 0.0;
            for (int off = 16; off; off >>= 1) {
                s += __shfl_down_sync(0xffffffffu, s, off);
                q += __shfl_down_sync(0xffffffffu, q, off);
            }
            if (!lane) { atomicAdd(&g_sum[0], s); atomicAdd(&g_sum[1], q); }
        }
    }
}

// ---------------- host launcher ----------------
extern "C" void kernel_launch(void* const* d_in, const int* in_sizes, int n_in,
                              void* d_out, int out_size)
{
    const float* x    = (const float*)d_in[0];
    const float* v1   = (const float*)d_in[1];
    const float* g1   = (const float*)d_in[2];
    const float* b1   = (const float*)d_in[3];
    const float* bn1g = (const float*)d_in[4];
    const float* bn1b = (const float*)d_in[5];
    const float* v2   = (const float*)d_in[6];
    const float* g2   = (const float*)d_in[7];
    const float* b2   = (const float*)d_in[8];
    const float* bn2g = (const float*)d_in[9];
    const float* bn2b = (const float*)d_in[10];
    const float* wf   = (const float*)d_in[11];
    const float* bf   = (const float*)d_in[12];
    float* out = (float*)d_out;

    const int SMEM_PREP  = (3 * H) * 4 + H * 4 + H * 129 * 4;                 // ~68 KB
    const int SMEM_APPLY = (NSEG * 64 + 64) * (int)sizeof(float4);            // 133120 B
    cudaFuncSetAttribute(k_prep,  cudaFuncAttributeMaxDynamicSharedMemorySize, SMEM_PREP);
    cudaFuncSetAttribute(k_apply, cudaFuncAttributeMaxDynamicSharedMemorySize, SMEM_APPLY);

    k_init<<<512, 256>>>(x);
    for (int l = 0; l < NLAYER; l++) {
        int uIdx = (l % 2 == 0) ? 1 : 0;
        int isLast = (l == NLAYER - 1) ? 1 : 0;
        k_prep<<<1, 256, SMEM_PREP>>>(l, v1, g1, b1, bn1g, bn1b, v2, g2, b2);
        k_hist<<<HIST_B, HIST_T>>>(uIdx);
        k_fold<<<H + 1, H>>>(l, bn2g, bn2b);
        k_scatter<<<SCAT_B, SCAT_T>>>();
        k_apply<<<148, 1024, SMEM_APPLY>>>(uIdx, isLast, l, wf, bf, out);
    }
    (void)in_sizes; (void)n_in; (void)out_size;
}